// round 3
// baseline (speedup 1.0000x reference)
#include <cuda_runtime.h>
#include <cstdint>

// GraphProjection: out[p] = concat(coord[p], bilerp(feat1..feat4))
// h = 250*(-Y)/(-Z) + 112, w = 250*X/(-Z) + 112, clipped to [0,223].
// Per level S in {56,28,14,7}: x = h/(224/S), y = w/(224/S); bilinear with
// floor/ceil corners, JAX-gather index clamping, weights from unclamped
// floor/ceil algebra (matches degenerate integer-coordinate cases exactly).

static constexpr int OUT_COLS = 963;

template <int C, int S>
__device__ __forceinline__ void bilerp_level(const float* __restrict__ feat,
                                             float x, float y,
                                             float* __restrict__ o, int lane) {
    float x1f = floorf(x), x2f = ceilf(x);
    float y1f = floorf(y), y2f = ceilf(y);
    int xi1 = (int)x1f;
    int xi2 = (int)x2f;
    int yi1 = (int)y1f;
    int yi2 = (int)y2f;
    // JAX gather clamps; also defensively clamp lower bound (NaN/denormal
    // conversion safety — keeps all addresses in-bounds no matter what).
    if (xi1 < 0) xi1 = 0;
    if (yi1 < 0) yi1 = 0;
    if (xi2 < 0) xi2 = 0;
    if (yi2 < 0) yi2 = 0;
    if (xi1 > S - 1) xi1 = S - 1;
    if (yi1 > S - 1) yi1 = S - 1;
    if (xi2 > S - 1) xi2 = S - 1;
    if (yi2 > S - 1) yi2 = S - 1;

    float w11 = (x2f - x) * (y2f - y);
    float w21 = (x - x1f) * (y2f - y);
    float w12 = (x2f - x) * (y - y1f);
    float w22 = (x - x1f) * (y - y1f);

    const float4* __restrict__ Q11 = (const float4*)(feat + (xi1 * S + yi1) * C);
    const float4* __restrict__ Q21 = (const float4*)(feat + (xi2 * S + yi1) * C);
    const float4* __restrict__ Q12 = (const float4*)(feat + (xi1 * S + yi2) * C);
    const float4* __restrict__ Q22 = (const float4*)(feat + (xi2 * S + yi2) * C);

    constexpr int NV = C / 4;
#pragma unroll
    for (int c4 = lane; c4 < NV; c4 += 32) {
        float4 a = __ldg(Q11 + c4);
        float4 b = __ldg(Q21 + c4);
        float4 c = __ldg(Q12 + c4);
        float4 d = __ldg(Q22 + c4);
        int c0 = c4 * 4;
        o[c0 + 0] = w11 * a.x + w21 * b.x + w12 * c.x + w22 * d.x;
        o[c0 + 1] = w11 * a.y + w21 * b.y + w12 * c.y + w22 * d.y;
        o[c0 + 2] = w11 * a.z + w21 * b.z + w12 * c.z + w22 * d.z;
        o[c0 + 3] = w11 * a.w + w21 * b.w + w12 * c.w + w22 * d.w;
    }
}

__global__ void __launch_bounds__(256)
graph_projection_kernel(const float* __restrict__ coord,
                        const float* __restrict__ f1,
                        const float* __restrict__ f2,
                        const float* __restrict__ f3,
                        const float* __restrict__ f4,
                        float* __restrict__ out, int N) {
    int gw = (blockIdx.x * blockDim.x + threadIdx.x) >> 5;  // warp id = point
    int lane = threadIdx.x & 31;
    if (gw >= N) return;
    int p = gw;

    float X = __ldg(coord + 3 * p + 0);
    float Y = __ldg(coord + 3 * p + 1);
    float Z = __ldg(coord + 3 * p + 2);

    float h = 250.0f * (-Y) / (-Z) + 112.0f;
    float w = 250.0f * X / (-Z) + 112.0f;
    // clip to [0,223]; comparison form preserves jnp.clip NaN propagation
    h = (h < 0.0f) ? 0.0f : ((h > 223.0f) ? 223.0f : h);
    w = (w < 0.0f) ? 0.0f : ((w > 223.0f) ? 223.0f : w);

    float* __restrict__ orow = out + (size_t)p * OUT_COLS;
    if (lane == 0) orow[0] = X;
    if (lane == 1) orow[1] = Y;
    if (lane == 2) orow[2] = Z;

    // scales: 224/56=4, 224/28=8, 224/14=16, 224/7=32 (exact pow2 -> mul ok)
    bilerp_level<64, 56>(f1, h * 0.25f,     w * 0.25f,     orow + 3,   lane);
    bilerp_level<128, 28>(f2, h * 0.125f,   w * 0.125f,    orow + 67,  lane);
    bilerp_level<256, 14>(f3, h * 0.0625f,  w * 0.0625f,   orow + 195, lane);
    bilerp_level<512, 7>(f4, h * 0.03125f,  w * 0.03125f,  orow + 451, lane);
}

extern "C" void kernel_launch(void* const* d_in, const int* in_sizes, int n_in,
                              void* d_out, int out_size) {
    const float* coord = (const float*)d_in[0];
    const float* f1 = (const float*)d_in[1];
    const float* f2 = (const float*)d_in[2];
    const float* f3 = (const float*)d_in[3];
    const float* f4 = (const float*)d_in[4];
    float* out = (float*)d_out;

    int N = in_sizes[0] / 3;

    // one warp per point, 8 warps per block
    int blocks = (N + 7) / 8;
    graph_projection_kernel<<<blocks, 256>>>(coord, f1, f2, f3, f4, out, N);
}

// round 4
// speedup vs baseline: 1.4625x; 1.4625x over previous
#include <cuda_runtime.h>
#include <cstdint>

// GraphProjection: out[p] = concat(coord[p], bilerp(feat1..feat4))
// h = 250*(-Y)/(-Z) + 112, w = 250*X/(-Z) + 112, clipped to [0,223].
// Per level S in {56,28,14,7}: x = h/(224/S), y = w/(224/S); bilinear with
// floor/ceil corners, JAX-gather index clamping, weights from unclamped
// floor/ceil algebra.
//
// R3 lesson (ncu): L1 was 81.4% busy, dominated by scattered STG.32 (lane
// stride 16B -> 4 wavefronts per store inst at 25% utilization). This round
// maps channel c -> lane (c & 31): stores are unit-stride coalesced (1 wf per
// 32 floats), loads stay full-line coalesced as scalar LDG.32.

static constexpr int OUT_COLS = 963;

template <int C, int S>
__device__ __forceinline__ void bilerp_level(const float* __restrict__ feat,
                                             float x, float y,
                                             float* __restrict__ o, int lane) {
    float x1f = floorf(x), x2f = ceilf(x);
    float y1f = floorf(y), y2f = ceilf(y);
    int xi1 = (int)x1f;
    int xi2 = (int)x2f;
    int yi1 = (int)y1f;
    int yi2 = (int)y2f;
    // JAX gather clamps; lower clamp also guards NaN->int conversions.
    if (xi1 < 0) xi1 = 0;
    if (yi1 < 0) yi1 = 0;
    if (xi2 < 0) xi2 = 0;
    if (yi2 < 0) yi2 = 0;
    if (xi1 > S - 1) xi1 = S - 1;
    if (yi1 > S - 1) yi1 = S - 1;
    if (xi2 > S - 1) xi2 = S - 1;
    if (yi2 > S - 1) yi2 = S - 1;

    float w11 = (x2f - x) * (y2f - y);
    float w21 = (x - x1f) * (y2f - y);
    float w12 = (x2f - x) * (y - y1f);
    float w22 = (x - x1f) * (y - y1f);

    const float* __restrict__ Q11 = feat + (xi1 * S + yi1) * C;
    const float* __restrict__ Q21 = feat + (xi2 * S + yi1) * C;
    const float* __restrict__ Q12 = feat + (xi1 * S + yi2) * C;
    const float* __restrict__ Q22 = feat + (xi2 * S + yi2) * C;

    // Unit-stride lane mapping: coalesced LDG.32 and (critically) coalesced
    // STG.32. Full unroll -> C/32 independent load batches in flight (MLP).
#pragma unroll
    for (int i = 0; i < C / 32; ++i) {
        int c = lane + 32 * i;
        float a = __ldg(Q11 + c);
        float b = __ldg(Q21 + c);
        float cc = __ldg(Q12 + c);
        float d = __ldg(Q22 + c);
        o[c] = w11 * a + w21 * b + w12 * cc + w22 * d;
    }
}

__global__ void __launch_bounds__(256)
graph_projection_kernel(const float* __restrict__ coord,
                        const float* __restrict__ f1,
                        const float* __restrict__ f2,
                        const float* __restrict__ f3,
                        const float* __restrict__ f4,
                        float* __restrict__ out, int N) {
    int gw = (blockIdx.x * blockDim.x + threadIdx.x) >> 5;  // warp id = point
    int lane = threadIdx.x & 31;
    if (gw >= N) return;
    int p = gw;

    float X = __ldg(coord + 3 * p + 0);
    float Y = __ldg(coord + 3 * p + 1);
    float Z = __ldg(coord + 3 * p + 2);

    float h = 250.0f * (-Y) / (-Z) + 112.0f;
    float w = 250.0f * X / (-Z) + 112.0f;
    // clip to [0,223]; comparison form preserves jnp.clip NaN propagation
    h = (h < 0.0f) ? 0.0f : ((h > 223.0f) ? 223.0f : h);
    w = (w < 0.0f) ? 0.0f : ((w > 223.0f) ? 223.0f : w);

    float* __restrict__ orow = out + (size_t)p * OUT_COLS;
    if (lane == 0) orow[0] = X;
    if (lane == 1) orow[1] = Y;
    if (lane == 2) orow[2] = Z;

    // scales: 224/56=4, 224/28=8, 224/14=16, 224/7=32 (exact pow2 -> mul ok)
    bilerp_level<64, 56>(f1, h * 0.25f,     w * 0.25f,     orow + 3,   lane);
    bilerp_level<128, 28>(f2, h * 0.125f,   w * 0.125f,    orow + 67,  lane);
    bilerp_level<256, 14>(f3, h * 0.0625f,  w * 0.0625f,   orow + 195, lane);
    bilerp_level<512, 7>(f4, h * 0.03125f,  w * 0.03125f,  orow + 451, lane);
}

extern "C" void kernel_launch(void* const* d_in, const int* in_sizes, int n_in,
                              void* d_out, int out_size) {
    const float* coord = (const float*)d_in[0];
    const float* f1 = (const float*)d_in[1];
    const float* f2 = (const float*)d_in[2];
    const float* f3 = (const float*)d_in[3];
    const float* f4 = (const float*)d_in[4];
    float* out = (float*)d_out;

    int N = in_sizes[0] / 3;

    // one warp per point, 8 warps per block
    int blocks = (N + 7) / 8;
    graph_projection_kernel<<<blocks, 256>>>(coord, f1, f2, f3, f4, out, N);
}